// round 1
// baseline (speedup 1.0000x reference)
#include <cuda_runtime.h>

// Problem constants (from reference)
#define BS_      8192
#define NS_      30          // N_STEPS
#define NC_      90          // N_COLS = NS*1*3
#define HB_      6           // half bandwidth of AtA
#define BW_      7           // band width (HB+1)

__global__ __launch_bounds__(32)
void ode_band_solve_kernel(const float* __restrict__ coeffs,  // (BS,30,1,1,3) -> (BS,90)
                           const float* __restrict__ rhs,     // (BS,30,1)     -> (BS,30)
                           const float* __restrict__ iv_rhs,  // (BS,2,1,2)    -> (BS,4)
                           const float* __restrict__ steps,   // (BS,29,1)     -> (BS,29)
                           float* __restrict__ out)           // (BS,30,1,3)   -> (BS,90)
{
    int b = blockIdx.x * blockDim.x + threadIdx.x;
    if (b >= BS_) return;

    // Lower band storage: B[j][k] = AtA[j+k][j], k=0..6
    double B[NC_][BW_];
    double r1[NC_];
    for (int j = 0; j < NC_; j++) {
        r1[j] = 0.0;
        #pragma unroll
        for (int k = 0; k < BW_; k++) B[j][k] = 0.0;
    }

    const float* c  = coeffs + (size_t)b * NC_;
    const float* rr = rhs    + (size_t)b * NS_;
    const float* iv = iv_rhs + (size_t)b * 4;
    const float* st = steps  + (size_t)b * (NS_ - 1);

    // ---- Equation rows: A[s, 3s+o] = coeffs[s,o] -------------------------
    for (int s = 0; s < NS_; s++) {
        double c0 = c[3*s + 0], c1 = c[3*s + 1], c2 = c[3*s + 2];
        int j = 3 * s;
        B[j  ][0] += c0*c0; B[j  ][1] += c1*c0; B[j  ][2] += c2*c0;
        B[j+1][0] += c1*c1; B[j+1][1] += c2*c1;
        B[j+2][0] += c2*c2;
        double rv = rr[s];
        r1[j] += c0*rv; r1[j+1] += c1*rv; r1[j+2] += c2*rv;
    }

    // ---- IV rows: unit entries at cols 0,1,3,4 ---------------------------
    B[0][0] += 1.0; B[1][0] += 1.0; B[3][0] += 1.0; B[4][0] += 1.0;
    r1[0] += iv[0]; r1[1] += iv[1]; r1[3] += iv[2]; r1[4] += iv[3];

    // ---- Smoothness rows (fwd + bwd Taylor), per interval s --------------
    for (int s = 0; s < NS_ - 1; s++) {
        double h  = st[s];
        double h2 = h * h;
        int j = 3 * s;
        // fwd i=0: cols j(1), j+1(h), j+2(h2/2), j+3(-1)
        {
            double v0 = 1.0, v1 = h, v2 = 0.5*h2, v3 = -1.0;
            B[j  ][0] += v0*v0; B[j  ][1] += v1*v0; B[j  ][2] += v2*v0; B[j  ][3] += v3*v0;
            B[j+1][0] += v1*v1; B[j+1][1] += v2*v1; B[j+1][2] += v3*v1;
            B[j+2][0] += v2*v2; B[j+2][1] += v3*v2;
            B[j+3][0] += v3*v3;
        }
        // fwd i=1: cols j+1(h), j+2(h2), j+4(-h)
        {
            double v1 = h, v2 = h2, v4 = -h;
            B[j+1][0] += v1*v1; B[j+1][1] += v2*v1; B[j+1][3] += v4*v1;
            B[j+2][0] += v2*v2; B[j+2][2] += v4*v2;
            B[j+4][0] += v4*v4;
        }
        // bwd i=0: cols j(-1), j+3(1), j+4(-h), j+5(h2/2)
        {
            double v0 = -1.0, v3 = 1.0, v4 = -h, v5 = 0.5*h2;
            B[j  ][0] += v0*v0; B[j  ][3] += v3*v0; B[j  ][4] += v4*v0; B[j  ][5] += v5*v0;
            B[j+3][0] += v3*v3; B[j+3][1] += v4*v3; B[j+3][2] += v5*v3;
            B[j+4][0] += v4*v4; B[j+4][1] += v5*v4;
            B[j+5][0] += v5*v5;
        }
        // bwd i=1: cols j+1(h), j+4(-h), j+5(h2)
        {
            double v1 = h, v4 = -h, v5 = h2;
            B[j+1][0] += v1*v1; B[j+1][3] += v4*v1; B[j+1][4] += v5*v1;
            B[j+4][0] += v4*v4; B[j+4][1] += v5*v4;
            B[j+5][0] += v5*v5;
        }
    }

    // ---- Central rows: s=1..28, cols 3s-2(-1), 3s+2(-(h_s+h_{s-1})), 3s+4(1)
    for (int s = 1; s < NS_ - 1; s++) {
        double cp = (double)st[s] + (double)st[s-1];
        int ja = 3*s - 2;
        double va = -1.0, vb = -cp, vc = 1.0;
        B[ja  ][0] += va*va; B[ja  ][4] += vb*va; B[ja  ][6] += vc*va;
        B[ja+4][0] += vb*vb; B[ja+4][2] += vc*vb;
        B[ja+6][0] += vc*vc;
    }

    // ---- Banded Cholesky (right-looking, in-place) ------------------------
    for (int j = 0; j < NC_; j++) {
        double d = sqrt(B[j][0]);
        double inv = 1.0 / d;
        B[j][0] = d;
        int kmax = NC_ - 1 - j; if (kmax > HB_) kmax = HB_;
        for (int k = 1; k <= kmax; k++) B[j][k] *= inv;
        for (int cc = 1; cc <= kmax; cc++) {
            double ljc = B[j][cc];
            for (int k = 0; k <= kmax - cc; k++)
                B[j + cc][k] -= B[j][cc + k] * ljc;
        }
    }

    // ---- Forward substitution: L y = r1 -----------------------------------
    double y[NC_];
    for (int j = 0; j < NC_; j++) {
        double s = r1[j];
        int qmax = j; if (qmax > HB_) qmax = HB_;
        for (int q = 1; q <= qmax; q++) s -= B[j - q][q] * y[j - q];
        y[j] = s / B[j][0];
    }

    // ---- Backward substitution: L^T x = y ---------------------------------
    double x[NC_];
    for (int j = NC_ - 1; j >= 0; j--) {
        double s = y[j];
        int qmax = NC_ - 1 - j; if (qmax > HB_) qmax = HB_;
        for (int q = 1; q <= qmax; q++) s -= B[j][q] * x[j + q];
        x[j] = s / B[j][0];
    }

    float* o = out + (size_t)b * NC_;
    for (int j = 0; j < NC_; j++) o[j] = (float)x[j];
}

extern "C" void kernel_launch(void* const* d_in, const int* in_sizes, int n_in,
                              void* d_out, int out_size) {
    const float* coeffs = (const float*)d_in[0];
    const float* rhs    = (const float*)d_in[1];
    const float* iv_rhs = (const float*)d_in[2];
    const float* steps  = (const float*)d_in[3];
    float* out = (float*)d_out;

    dim3 block(32);
    dim3 grid((BS_ + block.x - 1) / block.x);
    ode_band_solve_kernel<<<grid, block>>>(coeffs, rhs, iv_rhs, steps, out);
}

// round 2
// speedup vs baseline: 13.4377x; 13.4377x over previous
#include <cuda_runtime.h>

#define BS_ 8192
#define NS_ 30

// Streaming block-pentadiagonal Cholesky solve, 1 thread per batch element.
// Window state (all registers):
//   D0 (6): diag block (s,s) lower      D1 (6): diag block (s+1,s+1)
//   A  (9): block (s+1,s)               B1* (3): row 1 of block (s+2,s+1)
//   m1,m2 : live entries of block (s+2,s)   D211: [1][1] of diag (s+2,s+2)
//   r0 (3), r1 (3), r21: running reduced RHS
__global__ __launch_bounds__(32)
void ode_stream_kernel(const float* __restrict__ coeffs,
                       const float* __restrict__ rhs,
                       const float* __restrict__ ivr,
                       const float* __restrict__ steps,
                       float* __restrict__ out)
{
    int b = blockIdx.x * blockDim.x + threadIdx.x;
    if (b >= BS_) return;
    const float* c  = coeffs + (size_t)b * 90;
    const float* rr = rhs    + (size_t)b * 30;
    const float* iv = ivr    + (size_t)b * 4;
    const float* st = steps  + (size_t)b * 29;
    float* o = out + (size_t)b * 90;

    float sv[NS_ * 20];   // per-step factor + y, for back substitution

    float D000=0,D010=0,D020=0,D011=0,D021=0,D022=0;
    float D100=0,D110=0,D120=0,D111=0,D121=0,D122=0;
    float D211=0;
    float A00=0,A01=0,A02=0,A10=0,A11=0,A12=0,A20=0,A21=0,A22=0;
    float B10=0,B11=0,B12=0;
    float r00=0,r01=0,r02=0, r10=0,r11=0,r12=0, r21=0;

    float h = st[0];

    #pragma unroll 1
    for (int s = 0; s < NS_; s++) {
        // ---- assembly anchored at step s ----
        float c0=c[3*s], c1=c[3*s+1], c2=c[3*s+2], rv=rr[s];
        D000 += c0*c0; D010 += c1*c0; D020 += c2*c0;
        D011 += c1*c1; D021 += c2*c1; D022 += c2*c2;
        r00 += c0*rv; r01 += c1*rv; r02 += c2*rv;
        if (s == 0) { D000 += 1.f; D011 += 1.f; r00 += iv[0]; r01 += iv[1]; }
        if (s == 1) { D000 += 1.f; D011 += 1.f; r00 += iv[2]; r01 += iv[3]; }
        float m1 = 0.f, m2 = 0.f;
        if (s < NS_-1) {
            float h2 = h*h, h3 = h2*h, h4 = h2*h2;
            // fwd0 + fwd1 + bwd0 + bwd1 smoothness rows for interval s
            D000 += 2.f;       D010 += h;          D020 += 0.5f*h2;
            D011 += 3.f*h2;    D021 += 1.5f*h3;    D022 += 1.25f*h4;
            A00  += -2.f;      A01  += -h;         A02  += -0.5f*h2;
            A10  += h;         A11  += -2.f*h2;    A12  += -h3;
            A20  += -0.5f*h2;  A21  += h3;
            D100 += 2.f;       D110 += -h;         D120 += 0.5f*h2;
            D111 += 3.f*h2;    D121 += -1.5f*h3;   D122 += 1.25f*h4;
            float hn = 0.f;
            if (s < NS_-2) {
                hn = st[s+1];
                float cp = h + hn;          // central row t = s+1
                D011 += 1.f;  A21 += cp;  m1 = -1.f;
                D122 += cp*cp; B12 += -cp; D211 += 1.f;
            }
            h = hn;
        }

        // ---- factor 3x3 diag block ----
        float il00 = rsqrtf(D000);
        float l10 = D010*il00, l20 = D020*il00;
        float t11 = D011 - l10*l10;
        float il11 = rsqrtf(t11);
        float l21 = (D021 - l20*l10)*il11;
        float t22 = D022 - l20*l20 - l21*l21;
        float il22 = rsqrtf(t22);

        // ---- triangular solve of off-diag rows: w <- w * Ld^{-T} ----
        {
            float w0,w1,w2;
            w0 = A00*il00; w1 = (A01 - w0*l10)*il11; w2 = (A02 - w0*l20 - w1*l21)*il22;
            A00=w0; A01=w1; A02=w2;
            w0 = A10*il00; w1 = (A11 - w0*l10)*il11; w2 = (A12 - w0*l20 - w1*l21)*il22;
            A10=w0; A11=w1; A12=w2;
            w0 = A20*il00; w1 = (A21 - w0*l10)*il11; w2 = (A22 - w0*l20 - w1*l21)*il22;
            A20=w0; A21=w1; A22=w2;
        }
        m1 = m1*il11;
        m2 = -m1*l21*il22;

        // ---- forward substitution: y_s, then reduce trailing rhs ----
        float y0 = r00*il00;
        float y1 = (r01 - y0*l10)*il11;
        float y2 = (r02 - y0*l20 - y1*l21)*il22;
        r10 -= A00*y0 + A01*y1 + A02*y2;
        r11 -= A10*y0 + A11*y1 + A12*y2;
        r12 -= A20*y0 + A21*y1 + A22*y2;
        r21 -= m1*y1 + m2*y2;

        // ---- trailing Schur updates ----
        D100 -= A00*A00 + A01*A01 + A02*A02;
        D110 -= A10*A00 + A11*A01 + A12*A02;
        D120 -= A20*A00 + A21*A01 + A22*A02;
        D111 -= A10*A10 + A11*A11 + A12*A12;
        D121 -= A20*A10 + A21*A11 + A22*A12;
        D122 -= A20*A20 + A21*A21 + A22*A22;
        B10  -= m1*A01 + m2*A02;
        B11  -= m1*A11 + m2*A12;
        B12  -= m1*A21 + m2*A22;
        D211 -= m1*m1 + m2*m2;

        // ---- store factor for back substitution ----
        float* sp = sv + s*20;
        sp[0]=il00; sp[1]=l10; sp[2]=l20; sp[3]=il11; sp[4]=l21; sp[5]=il22;
        sp[6]=A00; sp[7]=A01; sp[8]=A02;
        sp[9]=A10; sp[10]=A11; sp[11]=A12;
        sp[12]=A20; sp[13]=A21; sp[14]=A22;
        sp[15]=m1; sp[16]=m2;
        sp[17]=y0; sp[18]=y1; sp[19]=y2;

        // ---- shift window ----
        D000=D100; D010=D110; D020=D120; D011=D111; D021=D121; D022=D122;
        D100=0; D110=0; D120=0; D111=D211; D121=0; D122=0; D211=0;
        A00=0; A01=0; A02=0; A10=B10; A11=B11; A12=B12; A20=0; A21=0; A22=0;
        B10=0; B11=0; B12=0;
        r00=r10; r01=r11; r02=r12;
        r10=0; r11=r21; r12=0; r21=0;
    }

    // ---- back substitution: x_s = Ld^{-T}(y_s - L10^T x_{s+1} - L20^T x_{s+2}) ----
    float xn0=0, xn1=0, xn2=0, xp1=0;
    #pragma unroll 1
    for (int s = NS_-1; s >= 0; s--) {
        const float* sp = sv + s*20;
        float il00=sp[0], l10=sp[1], l20=sp[2], il11=sp[3], l21=sp[4], il22=sp[5];
        float u0 = sp[17] - (sp[6]*xn0 + sp[9] *xn1 + sp[12]*xn2);
        float u1 = sp[18] - (sp[7]*xn0 + sp[10]*xn1 + sp[13]*xn2) - sp[15]*xp1;
        float u2 = sp[19] - (sp[8]*xn0 + sp[11]*xn1 + sp[14]*xn2) - sp[16]*xp1;
        float x2 = u2*il22;
        float x1 = (u1 - l21*x2)*il11;
        float x0 = (u0 - l10*x1 - l20*x2)*il00;
        o[3*s] = x0; o[3*s+1] = x1; o[3*s+2] = x2;
        xp1 = xn1; xn0 = x0; xn1 = x1; xn2 = x2;
    }
}

extern "C" void kernel_launch(void* const* d_in, const int* in_sizes, int n_in,
                              void* d_out, int out_size) {
    const float* coeffs = (const float*)d_in[0];
    const float* rhs    = (const float*)d_in[1];
    const float* iv_rhs = (const float*)d_in[2];
    const float* steps  = (const float*)d_in[3];
    float* out = (float*)d_out;

    dim3 block(32);
    dim3 grid((BS_ + block.x - 1) / block.x);
    ode_stream_kernel<<<grid, block>>>(coeffs, rhs, iv_rhs, steps, out);
}

// round 3
// speedup vs baseline: 16.0681x; 1.1957x over previous
#include <cuda_runtime.h>

#define BS_ 8192
#define NS_ 30

// Streaming block-pentadiagonal Cholesky solve, 1 thread per batch element.
// Round 3: prefetched global loads, float4 factor buffer, float2 output stores.
__global__ __launch_bounds__(32)
void ode_stream_kernel(const float* __restrict__ coeffs,
                       const float* __restrict__ rhs,
                       const float* __restrict__ ivr,
                       const float* __restrict__ steps,
                       float* __restrict__ out)
{
    int b = blockIdx.x * blockDim.x + threadIdx.x;
    if (b >= BS_) return;
    const float* c  = coeffs + (size_t)b * 90;
    const float* rr = rhs    + (size_t)b * 30;
    const float* iv = ivr    + (size_t)b * 4;
    const float* st = steps  + (size_t)b * 29;
    float* o = out + (size_t)b * 90;

    float4 sv4[NS_ * 5];   // per-step factor + y (write-once, read-once)

    float D000=0,D010=0,D020=0,D011=0,D021=0,D022=0;
    float D100=0,D110=0,D120=0,D111=0,D121=0,D122=0;
    float D211=0;
    float A00=0,A01=0,A02=0,A10=0,A11=0,A12=0,A20=0,A21=0,A22=0;
    float B10=0,B11=0,B12=0;
    float r00=0,r01=0,r02=0, r10=0,r11=0,r12=0, r21=0;

    // prefetch registers
    float pc0 = c[0], pc1 = c[1], pc2 = c[2], prv = rr[0];
    float h  = st[0];
    float hn = st[1];

    float iv0 = iv[0], iv1 = iv[1], iv2 = iv[2], iv3 = iv[3];

    #pragma unroll 1
    for (int s = 0; s < NS_; s++) {
        // consume prefetched values
        float c0 = pc0, c1 = pc1, c2 = pc2, rv = prv;
        // issue next iteration's loads NOW (latency hidden by the body)
        if (s < NS_-1) {
            pc0 = c[3*s+3]; pc1 = c[3*s+4]; pc2 = c[3*s+5];
            prv = rr[s+1];
        }
        float hn2 = (s + 2 <= NS_-2) ? st[s+2] : 0.f;

        // ---- assembly anchored at step s ----
        D000 += c0*c0; D010 += c1*c0; D020 += c2*c0;
        D011 += c1*c1; D021 += c2*c1; D022 += c2*c2;
        r00 += c0*rv; r01 += c1*rv; r02 += c2*rv;
        if (s == 0) { D000 += 1.f; D011 += 1.f; r00 += iv0; r01 += iv1; }
        if (s == 1) { D000 += 1.f; D011 += 1.f; r00 += iv2; r01 += iv3; }
        float m1 = 0.f, m2 = 0.f;
        if (s < NS_-1) {
            float h2 = h*h, h3 = h2*h, h4 = h2*h2;
            D000 += 2.f;       D010 += h;          D020 += 0.5f*h2;
            D011 += 3.f*h2;    D021 += 1.5f*h3;    D022 += 1.25f*h4;
            A00  += -2.f;      A01  += -h;         A02  += -0.5f*h2;
            A10  += h;         A11  += -2.f*h2;    A12  += -h3;
            A20  += -0.5f*h2;  A21  += h3;
            D100 += 2.f;       D110 += -h;         D120 += 0.5f*h2;
            D111 += 3.f*h2;    D121 += -1.5f*h3;   D122 += 1.25f*h4;
            if (s < NS_-2) {
                float cp = h + hn;          // central row t = s+1
                D011 += 1.f;  A21 += cp;  m1 = -1.f;
                D122 += cp*cp; B12 += -cp; D211 += 1.f;
            }
            h = hn; hn = hn2;
        }

        // ---- factor 3x3 diag block ----
        float il00 = rsqrtf(D000);
        float l10 = D010*il00, l20 = D020*il00;
        float t11 = D011 - l10*l10;
        float il11 = rsqrtf(t11);
        float l21 = (D021 - l20*l10)*il11;
        float t22 = D022 - l20*l20 - l21*l21;
        float il22 = rsqrtf(t22);

        // ---- triangular solve of off-diag rows: w <- w * Ld^{-T} ----
        {
            float w0,w1,w2;
            w0 = A00*il00; w1 = (A01 - w0*l10)*il11; w2 = (A02 - w0*l20 - w1*l21)*il22;
            A00=w0; A01=w1; A02=w2;
            w0 = A10*il00; w1 = (A11 - w0*l10)*il11; w2 = (A12 - w0*l20 - w1*l21)*il22;
            A10=w0; A11=w1; A12=w2;
            w0 = A20*il00; w1 = (A21 - w0*l10)*il11; w2 = (A22 - w0*l20 - w1*l21)*il22;
            A20=w0; A21=w1; A22=w2;
        }
        m1 = m1*il11;
        m2 = -m1*l21*il22;

        // ---- forward substitution ----
        float y0 = r00*il00;
        float y1 = (r01 - y0*l10)*il11;
        float y2 = (r02 - y0*l20 - y1*l21)*il22;
        r10 -= A00*y0 + A01*y1 + A02*y2;
        r11 -= A10*y0 + A11*y1 + A12*y2;
        r12 -= A20*y0 + A21*y1 + A22*y2;
        r21 -= m1*y1 + m2*y2;

        // ---- trailing Schur updates ----
        D100 -= A00*A00 + A01*A01 + A02*A02;
        D110 -= A10*A00 + A11*A01 + A12*A02;
        D120 -= A20*A00 + A21*A01 + A22*A02;
        D111 -= A10*A10 + A11*A11 + A12*A12;
        D121 -= A20*A10 + A21*A11 + A22*A12;
        D122 -= A20*A20 + A21*A21 + A22*A22;
        B10  -= m1*A01 + m2*A02;
        B11  -= m1*A11 + m2*A12;
        B12  -= m1*A21 + m2*A22;
        D211 -= m1*m1 + m2*m2;

        // ---- store factor (vectorized) ----
        float4* sp = sv4 + s*5;
        sp[0] = make_float4(il00, l10, l20, il11);
        sp[1] = make_float4(l21, il22, A00, A01);
        sp[2] = make_float4(A02, A10, A11, A12);
        sp[3] = make_float4(A20, A21, A22, m1);
        sp[4] = make_float4(m2, y0, y1, y2);

        // ---- shift window ----
        D000=D100; D010=D110; D020=D120; D011=D111; D021=D121; D022=D122;
        D100=0; D110=0; D120=0; D111=D211; D121=0; D122=0; D211=0;
        A00=0; A01=0; A02=0; A10=B10; A11=B11; A12=B12; A20=0; A21=0; A22=0;
        B10=0; B11=0; B12=0;
        r00=r10; r01=r11; r02=r12;
        r10=0; r11=r21; r12=0; r21=0;
    }

    // ---- back substitution with prefetch + float2 output packing ----
    float2* o2 = (float2*)o;   // row stride 360B is 8B-aligned
    float xn0=0, xn1=0, xn2=0, xp1=0;
    float carry = 0.f;

    float4 p0 = sv4[29*5+0], p1 = sv4[29*5+1], p2 = sv4[29*5+2],
           p3 = sv4[29*5+3], p4 = sv4[29*5+4];

    #pragma unroll 1
    for (int s = NS_-1; s >= 0; s--) {
        float4 q0 = p0, q1 = p1, q2 = p2, q3 = p3, q4 = p4;
        if (s > 0) {   // prefetch next step's factor off the chain
            const float4* np = sv4 + (s-1)*5;
            p0 = np[0]; p1 = np[1]; p2 = np[2]; p3 = np[3]; p4 = np[4];
        }
        float il00=q0.x, l10=q0.y, l20=q0.z, il11=q0.w;
        float l21=q1.x, il22=q1.y;
        float a00=q1.z, a01=q1.w, a02=q2.x;
        float a10=q2.y, a11=q2.z, a12=q2.w;
        float a20=q3.x, a21=q3.y, a22=q3.z;
        float m1=q3.w, m2=q4.x;
        float y0=q4.y, y1=q4.z, y2=q4.w;

        float u0 = y0 - (a00*xn0 + a10*xn1 + a20*xn2);
        float u1 = y1 - (a01*xn0 + a11*xn1 + a21*xn2) - m1*xp1;
        float u2 = y2 - (a02*xn0 + a12*xn1 + a22*xn2) - m2*xp1;
        float x2 = u2*il22;
        float x1 = (u1 - l21*x2)*il11;
        float x0 = (u0 - l10*x1 - l20*x2)*il00;

        // packed stores: indices 3s, 3s+1, 3s+2
        if (s & 1) {
            o2[(3*s+1) >> 1] = make_float2(x1, x2);   // (3s+1 even)
            carry = x0;                                // waits for x2 of s-1
        } else {
            o2[(3*s+2) >> 1] = make_float2(x2, carry); // (3s+2 even)
            o2[(3*s)   >> 1] = make_float2(x0, x1);    // (3s even)
        }

        xp1 = xn1; xn0 = x0; xn1 = x1; xn2 = x2;
    }
}

extern "C" void kernel_launch(void* const* d_in, const int* in_sizes, int n_in,
                              void* d_out, int out_size) {
    const float* coeffs = (const float*)d_in[0];
    const float* rhs    = (const float*)d_in[1];
    const float* iv_rhs = (const float*)d_in[2];
    const float* steps  = (const float*)d_in[3];
    float* out = (float*)d_out;

    dim3 block(32);
    dim3 grid((BS_ + block.x - 1) / block.x);
    ode_stream_kernel<<<grid, block>>>(coeffs, rhs, iv_rhs, steps, out);
}

// round 4
// speedup vs baseline: 17.3211x; 1.0780x over previous
#include <cuda_runtime.h>

#define BS_ 8192
#define NS_ 30
#define TPB 64

// Streaming block-pentadiagonal Cholesky solve, 1 thread per batch element.
// Round 4: smem-staged, fully coalesced global I/O.
__global__ __launch_bounds__(TPB)
void ode_stream_kernel(const float* __restrict__ coeffs,
                       const float* __restrict__ rhs,
                       const float* __restrict__ ivr,
                       const float* __restrict__ steps,
                       float* __restrict__ out)
{
    __shared__ float s_co[TPB * 90];   // coeffs in; reused for x out
    __shared__ float s_rr[TPB * 30];
    __shared__ float s_st[TPB * 29];
    __shared__ float s_iv[TPB * 4];

    const int tid = threadIdx.x;
    const size_t blk = (size_t)blockIdx.x * TPB;

    // ---- coalesced staging: global -> smem (float4) ----
    {
        const float4* g = (const float4*)(coeffs + blk * 90);
        float4* s = (float4*)s_co;
        #pragma unroll 4
        for (int k = tid; k < TPB*90/4; k += TPB) s[k] = g[k];
    }
    {
        const float4* g = (const float4*)(rhs + blk * 30);
        float4* s = (float4*)s_rr;
        #pragma unroll 4
        for (int k = tid; k < TPB*30/4; k += TPB) s[k] = g[k];
    }
    {
        const float4* g = (const float4*)(steps + blk * 29);
        float4* s = (float4*)s_st;
        #pragma unroll 4
        for (int k = tid; k < TPB*29/4; k += TPB) s[k] = g[k];
    }
    {
        const float4* g = (const float4*)(ivr + blk * 4);
        float4* s = (float4*)s_iv;
        for (int k = tid; k < TPB*4/4; k += TPB) s[k] = g[k];
    }
    __syncthreads();

    const float* c  = s_co + tid * 90;
    const float* rr = s_rr + tid * 30;
    const float* st = s_st + tid * 29;
    const float iv0 = s_iv[tid*4+0], iv1 = s_iv[tid*4+1],
                iv2 = s_iv[tid*4+2], iv3 = s_iv[tid*4+3];

    float4 sv4[NS_ * 5];   // per-step factor + y (local mem, write/read once)

    float D000=0,D010=0,D020=0,D011=0,D021=0,D022=0;
    float D100=0,D110=0,D120=0,D111=0,D121=0,D122=0;
    float D211=0;
    float A00=0,A01=0,A02=0,A10=0,A11=0,A12=0,A20=0,A21=0,A22=0;
    float B10=0,B11=0,B12=0;
    float r00=0,r01=0,r02=0, r10=0,r11=0,r12=0, r21=0;

    #pragma unroll 1
    for (int s = 0; s < NS_; s++) {
        float c0=c[3*s], c1=c[3*s+1], c2=c[3*s+2], rv=rr[s];

        // ---- assembly anchored at step s ----
        D000 += c0*c0; D010 += c1*c0; D020 += c2*c0;
        D011 += c1*c1; D021 += c2*c1; D022 += c2*c2;
        r00 += c0*rv; r01 += c1*rv; r02 += c2*rv;
        if (s == 0) { D000 += 1.f; D011 += 1.f; r00 += iv0; r01 += iv1; }
        if (s == 1) { D000 += 1.f; D011 += 1.f; r00 += iv2; r01 += iv3; }
        float m1 = 0.f, m2 = 0.f;
        if (s < NS_-1) {
            float h = st[s];
            float h2 = h*h, h3 = h2*h, h4 = h2*h2;
            D000 += 2.f;       D010 += h;          D020 += 0.5f*h2;
            D011 += 3.f*h2;    D021 += 1.5f*h3;    D022 += 1.25f*h4;
            A00  += -2.f;      A01  += -h;         A02  += -0.5f*h2;
            A10  += h;         A11  += -2.f*h2;    A12  += -h3;
            A20  += -0.5f*h2;  A21  += h3;
            D100 += 2.f;       D110 += -h;         D120 += 0.5f*h2;
            D111 += 3.f*h2;    D121 += -1.5f*h3;   D122 += 1.25f*h4;
            if (s < NS_-2) {
                float cp = h + st[s+1];     // central row t = s+1
                D011 += 1.f;  A21 += cp;  m1 = -1.f;
                D122 += cp*cp; B12 += -cp; D211 += 1.f;
            }
        }

        // ---- factor 3x3 diag block ----
        float il00 = rsqrtf(D000);
        float l10 = D010*il00, l20 = D020*il00;
        float t11 = D011 - l10*l10;
        float il11 = rsqrtf(t11);
        float l21 = (D021 - l20*l10)*il11;
        float t22 = D022 - l20*l20 - l21*l21;
        float il22 = rsqrtf(t22);

        // ---- triangular solve of off-diag rows: w <- w * Ld^{-T} ----
        {
            float w0,w1,w2;
            w0 = A00*il00; w1 = (A01 - w0*l10)*il11; w2 = (A02 - w0*l20 - w1*l21)*il22;
            A00=w0; A01=w1; A02=w2;
            w0 = A10*il00; w1 = (A11 - w0*l10)*il11; w2 = (A12 - w0*l20 - w1*l21)*il22;
            A10=w0; A11=w1; A12=w2;
            w0 = A20*il00; w1 = (A21 - w0*l10)*il11; w2 = (A22 - w0*l20 - w1*l21)*il22;
            A20=w0; A21=w1; A22=w2;
        }
        m1 = m1*il11;
        m2 = -m1*l21*il22;

        // ---- forward substitution ----
        float y0 = r00*il00;
        float y1 = (r01 - y0*l10)*il11;
        float y2 = (r02 - y0*l20 - y1*l21)*il22;
        r10 -= A00*y0 + A01*y1 + A02*y2;
        r11 -= A10*y0 + A11*y1 + A12*y2;
        r12 -= A20*y0 + A21*y1 + A22*y2;
        r21 -= m1*y1 + m2*y2;

        // ---- trailing Schur updates ----
        D100 -= A00*A00 + A01*A01 + A02*A02;
        D110 -= A10*A00 + A11*A01 + A12*A02;
        D120 -= A20*A00 + A21*A01 + A22*A02;
        D111 -= A10*A10 + A11*A11 + A12*A12;
        D121 -= A20*A10 + A21*A11 + A22*A12;
        D122 -= A20*A20 + A21*A21 + A22*A22;
        B10  -= m1*A01 + m2*A02;
        B11  -= m1*A11 + m2*A12;
        B12  -= m1*A21 + m2*A22;
        D211 -= m1*m1 + m2*m2;

        // ---- store factor (vectorized, local mem => coalesced) ----
        float4* sp = sv4 + s*5;
        sp[0] = make_float4(il00, l10, l20, il11);
        sp[1] = make_float4(l21, il22, A00, A01);
        sp[2] = make_float4(A02, A10, A11, A12);
        sp[3] = make_float4(A20, A21, A22, m1);
        sp[4] = make_float4(m2, y0, y1, y2);

        // ---- shift window ----
        D000=D100; D010=D110; D020=D120; D011=D111; D021=D121; D022=D122;
        D100=0; D110=0; D120=0; D111=D211; D121=0; D122=0; D211=0;
        A00=0; A01=0; A02=0; A10=B10; A11=B11; A12=B12; A20=0; A21=0; A22=0;
        B10=0; B11=0; B12=0;
        r00=r10; r01=r11; r02=r12;
        r10=0; r11=r21; r12=0; r21=0;
    }

    // ---- back substitution (prefetched local reads, smem writes) ----
    float* ox = s_co + tid * 90;   // coeffs consumed; reuse as output staging
    float xn0=0, xn1=0, xn2=0, xp1=0;

    float4 p0 = sv4[29*5+0], p1 = sv4[29*5+1], p2 = sv4[29*5+2],
           p3 = sv4[29*5+3], p4 = sv4[29*5+4];

    #pragma unroll 1
    for (int s = NS_-1; s >= 0; s--) {
        float4 q0 = p0, q1 = p1, q2 = p2, q3 = p3, q4 = p4;
        if (s > 0) {   // prefetch next step's factor off the chain
            const float4* np = sv4 + (s-1)*5;
            p0 = np[0]; p1 = np[1]; p2 = np[2]; p3 = np[3]; p4 = np[4];
        }
        float il00=q0.x, l10=q0.y, l20=q0.z, il11=q0.w;
        float l21=q1.x, il22=q1.y;
        float a00=q1.z, a01=q1.w, a02=q2.x;
        float a10=q2.y, a11=q2.z, a12=q2.w;
        float a20=q3.x, a21=q3.y, a22=q3.z;
        float m1=q3.w, m2=q4.x;
        float y0=q4.y, y1=q4.z, y2=q4.w;

        float u0 = y0 - (a00*xn0 + a10*xn1 + a20*xn2);
        float u1 = y1 - (a01*xn0 + a11*xn1 + a21*xn2) - m1*xp1;
        float u2 = y2 - (a02*xn0 + a12*xn1 + a22*xn2) - m2*xp1;
        float x2 = u2*il22;
        float x1 = (u1 - l21*x2)*il11;
        float x0 = (u0 - l10*x1 - l20*x2)*il00;

        ox[3*s] = x0; ox[3*s+1] = x1; ox[3*s+2] = x2;

        xp1 = xn1; xn0 = x0; xn1 = x1; xn2 = x2;
    }

    // ---- coalesced store-out: smem -> global (float4) ----
    __syncthreads();
    {
        const float4* s = (const float4*)s_co;
        float4* g = (float4*)(out + blk * 90);
        #pragma unroll 4
        for (int k = tid; k < TPB*90/4; k += TPB) g[k] = s[k];
    }
}

extern "C" void kernel_launch(void* const* d_in, const int* in_sizes, int n_in,
                              void* d_out, int out_size) {
    const float* coeffs = (const float*)d_in[0];
    const float* rhs    = (const float*)d_in[1];
    const float* iv_rhs = (const float*)d_in[2];
    const float* steps  = (const float*)d_in[3];
    float* out = (float*)d_out;

    dim3 block(TPB);
    dim3 grid(BS_ / TPB);
    ode_stream_kernel<<<grid, block>>>(coeffs, rhs, iv_rhs, steps, out);
}

// round 5
// speedup vs baseline: 22.0819x; 1.2749x over previous
#include <cuda_runtime.h>

#define BS_ 8192
#define NS_ 30
#define TPB 64

// Streaming block-pentadiagonal Cholesky solve, 1 thread per batch element.
// Round 5: fully unrolled forward + backward passes (cross-step ILP, no shift
// MOVs, compile-time step specialization). Coalesced smem-staged I/O kept.
__global__ __launch_bounds__(TPB)
void ode_stream_kernel(const float* __restrict__ coeffs,
                       const float* __restrict__ rhs,
                       const float* __restrict__ ivr,
                       const float* __restrict__ steps,
                       float* __restrict__ out)
{
    __shared__ float s_co[TPB * 90];   // coeffs in; reused for x out
    __shared__ float s_rr[TPB * 30];
    __shared__ float s_st[TPB * 29];
    __shared__ float s_iv[TPB * 4];

    const int tid = threadIdx.x;
    const size_t blk = (size_t)blockIdx.x * TPB;

    // ---- coalesced staging: global -> smem (float4) ----
    {
        const float4* g = (const float4*)(coeffs + blk * 90);
        float4* s = (float4*)s_co;
        #pragma unroll
        for (int i = 0; i < 90/4; i++) s[i*TPB + tid] = g[i*TPB + tid];
        // 90*TPB/4 = 1440 = 22.5*TPB; handle remainder generically:
        for (int k = (90/4)*TPB + tid; k < TPB*90/4; k += TPB) s[k] = g[k];
    }
    {
        const float4* g = (const float4*)(rhs + blk * 30);
        float4* s = (float4*)s_rr;
        #pragma unroll
        for (int i = 0; i < 30/4; i++) s[i*TPB + tid] = g[i*TPB + tid];
        for (int k = (30/4)*TPB + tid; k < TPB*30/4; k += TPB) s[k] = g[k];
    }
    {
        const float4* g = (const float4*)(steps + blk * 29);
        float4* s = (float4*)s_st;
        #pragma unroll
        for (int i = 0; i < 29/4; i++) s[i*TPB + tid] = g[i*TPB + tid];
        for (int k = (29/4)*TPB + tid; k < TPB*29/4; k += TPB) s[k] = g[k];
    }
    {
        const float4* g = (const float4*)(ivr + blk * 4);
        float4* s = (float4*)s_iv;
        s[tid] = g[tid];
    }
    __syncthreads();

    const float* c  = s_co + tid * 90;
    const float* rr = s_rr + tid * 30;
    const float* st = s_st + tid * 29;
    const float iv0 = s_iv[tid*4+0], iv1 = s_iv[tid*4+1],
                iv2 = s_iv[tid*4+2], iv3 = s_iv[tid*4+3];

    float4 sv4[NS_ * 5];   // per-step factor + y (local mem, write/read once)

    float D000=0,D010=0,D020=0,D011=0,D021=0,D022=0;
    float D100=0,D110=0,D120=0,D111=0,D121=0,D122=0;
    float D211=0;
    float A00=0,A01=0,A02=0,A10=0,A11=0,A12=0,A20=0,A21=0,A22=0;
    float B10=0,B11=0,B12=0;
    float r00=0,r01=0,r02=0, r10=0,r11=0,r12=0, r21=0;

    #pragma unroll
    for (int s = 0; s < NS_; s++) {
        float c0=c[3*s], c1=c[3*s+1], c2=c[3*s+2], rv=rr[s];

        // ---- assembly anchored at step s ----
        D000 += c0*c0; D010 += c1*c0; D020 += c2*c0;
        D011 += c1*c1; D021 += c2*c1; D022 += c2*c2;
        r00 += c0*rv; r01 += c1*rv; r02 += c2*rv;
        if (s == 0) { D000 += 1.f; D011 += 1.f; r00 += iv0; r01 += iv1; }
        if (s == 1) { D000 += 1.f; D011 += 1.f; r00 += iv2; r01 += iv3; }
        float m1 = 0.f, m2 = 0.f;
        if (s < NS_-1) {
            float h = st[s];
            float h2 = h*h, h3 = h2*h, h4 = h2*h2;
            D000 += 2.f;       D010 += h;          D020 += 0.5f*h2;
            D011 += 3.f*h2;    D021 += 1.5f*h3;    D022 += 1.25f*h4;
            A00  += -2.f;      A01  += -h;         A02  += -0.5f*h2;
            A10  += h;         A11  += -2.f*h2;    A12  += -h3;
            A20  += -0.5f*h2;  A21  += h3;
            D100 += 2.f;       D110 += -h;         D120 += 0.5f*h2;
            D111 += 3.f*h2;    D121 += -1.5f*h3;   D122 += 1.25f*h4;
            if (s < NS_-2) {
                float cp = h + st[s+1];     // central row t = s+1
                D011 += 1.f;  A21 += cp;  m1 = -1.f;
                D122 += cp*cp; B12 += -cp; D211 += 1.f;
            }
        }

        // ---- factor 3x3 diag block ----
        float il00 = rsqrtf(D000);
        float l10 = D010*il00, l20 = D020*il00;
        float t11 = D011 - l10*l10;
        float il11 = rsqrtf(t11);
        float l21 = (D021 - l20*l10)*il11;
        float t22 = D022 - l20*l20 - l21*l21;
        float il22 = rsqrtf(t22);

        // ---- triangular solve of off-diag rows: w <- w * Ld^{-T} ----
        {
            float w0,w1,w2;
            w0 = A00*il00; w1 = (A01 - w0*l10)*il11; w2 = (A02 - w0*l20 - w1*l21)*il22;
            A00=w0; A01=w1; A02=w2;
            w0 = A10*il00; w1 = (A11 - w0*l10)*il11; w2 = (A12 - w0*l20 - w1*l21)*il22;
            A10=w0; A11=w1; A12=w2;
            w0 = A20*il00; w1 = (A21 - w0*l10)*il11; w2 = (A22 - w0*l20 - w1*l21)*il22;
            A20=w0; A21=w1; A22=w2;
        }
        m1 = m1*il11;
        m2 = -m1*l21*il22;

        // ---- forward substitution ----
        float y0 = r00*il00;
        float y1 = (r01 - y0*l10)*il11;
        float y2 = (r02 - y0*l20 - y1*l21)*il22;
        r10 -= A00*y0 + A01*y1 + A02*y2;
        r11 -= A10*y0 + A11*y1 + A12*y2;
        r12 -= A20*y0 + A21*y1 + A22*y2;
        r21 -= m1*y1 + m2*y2;

        // ---- trailing Schur updates ----
        D100 -= A00*A00 + A01*A01 + A02*A02;
        D110 -= A10*A00 + A11*A01 + A12*A02;
        D120 -= A20*A00 + A21*A01 + A22*A02;
        D111 -= A10*A10 + A11*A11 + A12*A12;
        D121 -= A20*A10 + A21*A11 + A22*A12;
        D122 -= A20*A20 + A21*A21 + A22*A22;
        B10  -= m1*A01 + m2*A02;
        B11  -= m1*A11 + m2*A12;
        B12  -= m1*A21 + m2*A22;
        D211 -= m1*m1 + m2*m2;

        // ---- store factor (vectorized, local mem => coalesced) ----
        float4* sp = sv4 + s*5;
        sp[0] = make_float4(il00, l10, l20, il11);
        sp[1] = make_float4(l21, il22, A00, A01);
        sp[2] = make_float4(A02, A10, A11, A12);
        sp[3] = make_float4(A20, A21, A22, m1);
        sp[4] = make_float4(m2, y0, y1, y2);

        // ---- shift window (pure renaming after full unroll) ----
        D000=D100; D010=D110; D020=D120; D011=D111; D021=D121; D022=D122;
        D100=0; D110=0; D120=0; D111=D211; D121=0; D122=0; D211=0;
        A00=0; A01=0; A02=0; A10=B10; A11=B11; A12=B12; A20=0; A21=0; A22=0;
        B10=0; B11=0; B12=0;
        r00=r10; r01=r11; r02=r12;
        r10=0; r11=r21; r12=0; r21=0;
    }

    // ---- back substitution (fully unrolled; loads scheduled early) ----
    float* ox = s_co + tid * 90;   // coeffs consumed; reuse as output staging
    float xn0=0, xn1=0, xn2=0, xp1=0;

    #pragma unroll
    for (int s = NS_-1; s >= 0; s--) {
        const float4* sp = sv4 + s*5;
        float4 q0 = sp[0], q1 = sp[1], q2 = sp[2], q3 = sp[3], q4 = sp[4];

        float il00=q0.x, l10=q0.y, l20=q0.z, il11=q0.w;
        float l21=q1.x, il22=q1.y;
        float a00=q1.z, a01=q1.w, a02=q2.x;
        float a10=q2.y, a11=q2.z, a12=q2.w;
        float a20=q3.x, a21=q3.y, a22=q3.z;
        float m1=q3.w, m2=q4.x;
        float y0=q4.y, y1=q4.z, y2=q4.w;

        float u0 = y0 - (a00*xn0 + a10*xn1 + a20*xn2);
        float u1 = y1 - (a01*xn0 + a11*xn1 + a21*xn2) - m1*xp1;
        float u2 = y2 - (a02*xn0 + a12*xn1 + a22*xn2) - m2*xp1;
        float x2 = u2*il22;
        float x1 = (u1 - l21*x2)*il11;
        float x0 = (u0 - l10*x1 - l20*x2)*il00;

        ox[3*s] = x0; ox[3*s+1] = x1; ox[3*s+2] = x2;

        xp1 = xn1; xn0 = x0; xn1 = x1; xn2 = x2;
    }

    // ---- coalesced store-out: smem -> global (float4) ----
    __syncthreads();
    {
        const float4* s = (const float4*)s_co;
        float4* g = (float4*)(out + blk * 90);
        #pragma unroll
        for (int i = 0; i < 90/4; i++) g[i*TPB + tid] = s[i*TPB + tid];
        for (int k = (90/4)*TPB + tid; k < TPB*90/4; k += TPB) g[k] = s[k];
    }
}

extern "C" void kernel_launch(void* const* d_in, const int* in_sizes, int n_in,
                              void* d_out, int out_size) {
    const float* coeffs = (const float*)d_in[0];
    const float* rhs    = (const float*)d_in[1];
    const float* iv_rhs = (const float*)d_in[2];
    const float* steps  = (const float*)d_in[3];
    float* out = (float*)d_out;

    dim3 block(TPB);
    dim3 grid(BS_ / TPB);
    ode_stream_kernel<<<grid, block>>>(coeffs, rhs, iv_rhs, steps, out);
}

// round 6
// speedup vs baseline: 23.4050x; 1.0599x over previous
#include <cuda_runtime.h>

#define BS_  8192
#define NS_  30
#define KH_  14      // top eliminates 0..13, bottom 29..16, interface 14,15
#define E_   64      // elements per block
#define TPB  128     // warps 0-1: top halves, warps 2-3: bottom halves

// Generic streaming block elimination step (shared by both directions).
// Window vars: D0 (6), D1 (6), D211, A (9), B row1 (3), r0 (3), r1 (3), r21, m1.
#define ELIM_STEP(SVIDX) do {                                                    \
    float il00 = rsqrtf(D000);                                                   \
    float l10 = D010*il00, l20 = D020*il00;                                      \
    float il11 = rsqrtf(D011 - l10*l10);                                         \
    float l21 = (D021 - l20*l10)*il11;                                           \
    float il22 = rsqrtf(D022 - l20*l20 - l21*l21);                               \
    float w0,w1,w2;                                                              \
    w0 = A00*il00; w1 = (A01 - w0*l10)*il11; w2 = (A02 - w0*l20 - w1*l21)*il22;  \
    A00=w0; A01=w1; A02=w2;                                                      \
    w0 = A10*il00; w1 = (A11 - w0*l10)*il11; w2 = (A12 - w0*l20 - w1*l21)*il22;  \
    A10=w0; A11=w1; A12=w2;                                                      \
    w0 = A20*il00; w1 = (A21 - w0*l10)*il11; w2 = (A22 - w0*l20 - w1*l21)*il22;  \
    A20=w0; A21=w1; A22=w2;                                                      \
    m1 = m1*il11;                                                                \
    float m2 = -m1*l21*il22;                                                     \
    float y0 = r00*il00;                                                         \
    float y1 = (r01 - y0*l10)*il11;                                              \
    float y2 = (r02 - y0*l20 - y1*l21)*il22;                                     \
    r10 -= A00*y0 + A01*y1 + A02*y2;                                             \
    r11 -= A10*y0 + A11*y1 + A12*y2;                                             \
    r12 -= A20*y0 + A21*y1 + A22*y2;                                             \
    r21 -= m1*y1 + m2*y2;                                                        \
    D100 -= A00*A00 + A01*A01 + A02*A02;                                         \
    D110 -= A10*A00 + A11*A01 + A12*A02;                                         \
    D120 -= A20*A00 + A21*A01 + A22*A02;                                         \
    D111 -= A10*A10 + A11*A11 + A12*A12;                                         \
    D121 -= A20*A10 + A21*A11 + A22*A12;                                         \
    D122 -= A20*A20 + A21*A21 + A22*A22;                                         \
    B10 -= m1*A01 + m2*A02;                                                      \
    B11 -= m1*A11 + m2*A12;                                                      \
    B12 -= m1*A21 + m2*A22;                                                      \
    D211 -= m1*m1 + m2*m2;                                                       \
    float4* sp = sv4 + (SVIDX)*5;                                                \
    sp[0] = make_float4(il00, l10, l20, il11);                                   \
    sp[1] = make_float4(l21, il22, A00, A01);                                    \
    sp[2] = make_float4(A02, A10, A11, A12);                                     \
    sp[3] = make_float4(A20, A21, A22, m1);                                      \
    sp[4] = make_float4(m2, y0, y1, y2);                                         \
    D000=D100; D010=D110; D020=D120; D011=D111; D021=D121; D022=D122;            \
    D100=0; D110=0; D120=0; D111=D211; D121=0; D122=0; D211=0;                   \
    A00=0; A01=0; A02=0; A10=B10; A11=B11; A12=B12; A20=0; A21=0; A22=0;         \
    B10=0; B11=0; B12=0;                                                         \
    r00=r10; r01=r11; r02=r12;                                                   \
    r10=0; r11=r21; r12=0; r21=0;                                                \
} while(0)

__global__ __launch_bounds__(TPB)
void ode_babe_kernel(const float* __restrict__ coeffs,
                     const float* __restrict__ rhs,
                     const float* __restrict__ ivr,
                     const float* __restrict__ steps,
                     float* __restrict__ out)
{
    __shared__ float s_co[E_ * 90];   // coeffs in; reused for x out
    __shared__ float s_rr[E_ * 30];
    __shared__ float s_st[E_ * 29];
    __shared__ float s_iv[E_ * 4];
    __shared__ float s_ex[E_ * 2 * 16];   // interface exchange: [elem][top/bot][14]

    const int tid = threadIdx.x;
    const size_t blk = (size_t)blockIdx.x * E_;

    // ---- coalesced staging ----
    {
        const float4* g = (const float4*)(coeffs + blk * 90);
        float4* s = (float4*)s_co;
        for (int k = tid; k < E_*90/4; k += TPB) s[k] = g[k];
    }
    {
        const float4* g = (const float4*)(rhs + blk * 30);
        float4* s = (float4*)s_rr;
        for (int k = tid; k < E_*30/4; k += TPB) s[k] = g[k];
    }
    {
        const float4* g = (const float4*)(steps + blk * 29);
        float4* s = (float4*)s_st;
        for (int k = tid; k < E_*29/4; k += TPB) s[k] = g[k];
    }
    {
        const float4* g = (const float4*)(ivr + blk * 4);
        float4* s = (float4*)s_iv;
        for (int k = tid; k < E_*4/4; k += TPB) s[k] = g[k];
    }
    __syncthreads();

    const int  e   = tid & (E_ - 1);
    const bool top = tid < E_;

    const float* cc  = s_co + e * 90;
    const float* rrp = s_rr + e * 30;
    const float* stp = s_st + e * 29;

    float4 sv4[KH_ * 5];

    float D000=0,D010=0,D020=0,D011=0,D021=0,D022=0;
    float D100=0,D110=0,D120=0,D111=0,D121=0,D122=0;
    float D211=0;
    float A00=0,A01=0,A02=0,A10=0,A11=0,A12=0,A20=0,A21=0,A22=0;
    float B10=0,B11=0,B12=0;
    float r00=0,r01=0,r02=0, r10=0,r11=0,r12=0, r21=0;

    if (top) {
        const float iv0 = s_iv[e*4+0], iv1 = s_iv[e*4+1],
                    iv2 = s_iv[e*4+2], iv3 = s_iv[e*4+3];
        #pragma unroll
        for (int s = 0; s < KH_; s++) {
            float c0=cc[3*s], c1=cc[3*s+1], c2=cc[3*s+2], rv=rrp[s];
            D000 += c0*c0; D010 += c1*c0; D020 += c2*c0;
            D011 += c1*c1; D021 += c2*c1; D022 += c2*c2;
            r00 += c0*rv; r01 += c1*rv; r02 += c2*rv;
            if (s == 0) { D000 += 1.f; D011 += 1.f; r00 += iv0; r01 += iv1; }
            if (s == 1) { D000 += 1.f; D011 += 1.f; r00 += iv2; r01 += iv3; }
            float h = stp[s];
            float h2 = h*h, h3 = h2*h, h4 = h2*h2;
            D000 += 2.f;       D010 += h;          D020 += 0.5f*h2;
            D011 += 3.f*h2;    D021 += 1.5f*h3;    D022 += 1.25f*h4;
            A00  += -2.f;      A01  += -h;         A02  += -0.5f*h2;
            A10  += h;         A11  += -2.f*h2;    A12  += -h3;
            A20  += -0.5f*h2;  A21  += h3;
            D100 += 2.f;       D110 += -h;         D120 += 0.5f*h2;
            D111 += 3.f*h2;    D121 += -1.5f*h3;   D122 += 1.25f*h4;
            float cp = h + stp[s+1];                  // central row t = s+1
            D011 += 1.f;  A21 += cp;  float m1 = -1.f;
            D122 += cp*cp; B12 += -cp; D211 += 1.f;
            ELIM_STEP(s);
        }
    } else {
        #pragma unroll
        for (int u = 0; u < KH_; u++) {
            const int s = 29 - u;                     // original step index
            float c0=cc[3*s], c1=cc[3*s+1], c2=cc[3*s+2], rv=rrp[s];
            D000 += c0*c0; D010 += c1*c0; D020 += c2*c0;
            D011 += c1*c1; D021 += c2*c1; D022 += c2*c2;
            r00 += c0*rv; r01 += c1*rv; r02 += c2*rv;
            float h = stp[s-1];                       // interval s-1
            float h2 = h*h, h3 = h2*h, h4 = h2*h2;
            // D'_u = D_s gets interval-(s-1) D1-group:
            D000 += 2.f;       D010 += -h;         D020 += 0.5f*h2;
            D011 += 3.f*h2;    D021 += -1.5f*h3;   D022 += 1.25f*h4;
            // A'_u = A_{s-1}^T:
            A00  += -2.f;      A01  += h;          A02  += -0.5f*h2;
            A10  += -h;        A11  += -2.f*h2;    A12  += h3;
            A20  += -0.5f*h2;  A21  += -h3;
            // D'_{u+1} = D_{s-1} gets D0-group:
            D100 += 2.f;       D110 += h;          D120 += 0.5f*h2;
            D111 += 3.f*h2;    D121 += 1.5f*h3;    D122 += 1.25f*h4;
            // central row t = s-1, cp = h_{s-2} + h_{s-1}:
            float cp = stp[s-2] + h;
            D011 += 1.f;  A21 += -cp;  float m1 = -1.f;
            D122 += cp*cp; B12 += cp; D211 += 1.f;
            ELIM_STEP(u);
        }
    }

    // ---- export window carries (14 floats) ----
    {
        float* ex = s_ex + (e*2 + (top ? 0 : 1)) * 16;
        ex[0]=D000; ex[1]=D010; ex[2]=D020; ex[3]=D011; ex[4]=D021; ex[5]=D022;
        ex[6]=D111;                 // carry into far diag [1][1]
        ex[7]=A10; ex[8]=A11; ex[9]=A12;   // B-carry row
        ex[10]=r00; ex[11]=r01; ex[12]=r02;
        ex[13]=r11;                 // rhs carry [1]
    }
    __syncthreads();

    // ---- interface: 6x6 SPD solve for x_14, x_15 (redundant on both threads) ----
    float x10_, x11_, x12_, x20_, x21_, x22_;
    {
        const float* te = s_ex + (e*2 + 0) * 16;
        const float* be = s_ex + (e*2 + 1) * 16;
        float h = stp[KH_];
        float h2 = h*h, h3 = h2*h, h4 = h2*h2;
        float cK0=cc[3*KH_], cK1=cc[3*KH_+1], cK2=cc[3*KH_+2];
        float cL0=cc[3*KH_+3], cL1=cc[3*KH_+4], cL2=cc[3*KH_+5];
        float rvK = rrp[KH_], rvL = rrp[KH_+1];

        // D_14
        float d00 = te[0] + cK0*cK0 + 2.f;
        float d10 = te[1] + cK1*cK0 + h;
        float d20 = te[2] + cK2*cK0 + 0.5f*h2;
        float d11 = te[3] + cK1*cK1 + 3.f*h2 + be[6];
        float d21 = te[4] + cK2*cK1 + 1.5f*h3;
        float d22 = te[5] + cK2*cK2 + 1.25f*h4;
        // D_15
        float e00 = be[0] + cL0*cL0 + 2.f;
        float e10 = be[1] + cL1*cL0 - h;
        float e20 = be[2] + cL2*cL0 + 0.5f*h2;
        float e11 = be[3] + cL1*cL1 + 3.f*h2 + te[6];
        float e21 = be[4] + cL2*cL1 - 1.5f*h3;
        float e22 = be[5] + cL2*cL2 + 1.25f*h4;
        // A = block(15,14): interval-14 group + top row-1 carry + bottom col-1 carry
        float a00 = -2.f;
        float a01 = -h        + be[7];
        float a02 = -0.5f*h2;
        float a10 =  h        + te[7];
        float a11 = -2.f*h2   + te[8] + be[8];
        float a12 = -h3       + te[9];
        float a20 = -0.5f*h2;
        float a21 =  h3       + be[9];
        float a22 = 0.f;
        // rhs
        float rk0 = te[10] + cK0*rvK;
        float rk1 = te[11] + cK1*rvK + be[13];
        float rk2 = te[12] + cK2*rvK;
        float rl0 = be[10] + cL0*rvL;
        float rl1 = be[11] + cL1*rvL + te[13];
        float rl2 = be[12] + cL2*rvL;

        // chol(D_14)
        float il00 = rsqrtf(d00);
        float l10 = d10*il00, l20 = d20*il00;
        float il11 = rsqrtf(d11 - l10*l10);
        float l21 = (d21 - l20*l10)*il11;
        float il22 = rsqrtf(d22 - l20*l20 - l21*l21);
        // W = A * L^{-T}
        float w00 = a00*il00, w01 = (a01 - w00*l10)*il11, w02 = (a02 - w00*l20 - w01*l21)*il22;
        float w10 = a10*il00, w11 = (a11 - w10*l10)*il11, w12 = (a12 - w10*l20 - w11*l21)*il22;
        float w20 = a20*il00, w21 = (a21 - w20*l10)*il11, w22 = (a22 - w20*l20 - w21*l21)*il22;
        // S = D_15 - W W^T
        float s00 = e00 - (w00*w00 + w01*w01 + w02*w02);
        float s10 = e10 - (w10*w00 + w11*w01 + w12*w02);
        float s20 = e20 - (w20*w00 + w21*w01 + w22*w02);
        float s11 = e11 - (w10*w10 + w11*w11 + w12*w12);
        float s21 = e21 - (w20*w10 + w21*w11 + w22*w12);
        float s22 = e22 - (w20*w20 + w21*w21 + w22*w22);
        float jl00 = rsqrtf(s00);
        float k10 = s10*jl00, k20 = s20*jl00;
        float jl11 = rsqrtf(s11 - k10*k10);
        float k21 = (s21 - k20*k10)*jl11;
        float jl22 = rsqrtf(s22 - k20*k20 - k21*k21);
        // forward
        float y10 = rk0*il00;
        float y11 = (rk1 - y10*l10)*il11;
        float y12 = (rk2 - y10*l20 - y11*l21)*il22;
        float t0 = rl0 - (w00*y10 + w01*y11 + w02*y12);
        float t1 = rl1 - (w10*y10 + w11*y11 + w12*y12);
        float t2 = rl2 - (w20*y10 + w21*y11 + w22*y12);
        float y20 = t0*jl00;
        float y21 = (t1 - y20*k10)*jl11;
        float y22 = (t2 - y20*k20 - y21*k21)*jl22;
        // backward
        x22_ = y22*jl22;
        x21_ = (y21 - k21*x22_)*jl11;
        x20_ = (y20 - k10*x21_ - k20*x22_)*jl00;
        float z0 = y10 - (w00*x20_ + w10*x21_ + w20*x22_);
        float z1 = y11 - (w01*x20_ + w11*x21_ + w21*x22_);
        float z2 = y12 - (w02*x20_ + w12*x21_ + w22*x22_);
        x12_ = z2*il22;
        x11_ = (z1 - l21*x12_)*il11;
        x10_ = (z0 - l10*x11_ - l20*x12_)*il00;
    }

    // ---- back substitution (both halves in parallel) ----
    float* ox = s_co + e * 90;   // coeffs consumed; reuse as output staging

    if (top) {
        ox[3*KH_+0]=x10_; ox[3*KH_+1]=x11_; ox[3*KH_+2]=x12_;
        ox[3*KH_+3]=x20_; ox[3*KH_+4]=x21_; ox[3*KH_+5]=x22_;
        float xn0=x10_, xn1=x11_, xn2=x12_, xp1=x21_;
        #pragma unroll
        for (int s = KH_-1; s >= 0; s--) {
            const float4* sp = sv4 + s*5;
            float4 q0 = sp[0], q1 = sp[1], q2 = sp[2], q3 = sp[3], q4 = sp[4];
            float u0 = q4.y - (q1.z*xn0 + q2.y*xn1 + q3.x*xn2);
            float u1 = q4.z - (q1.w*xn0 + q2.z*xn1 + q3.y*xn2) - q3.w*xp1;
            float u2 = q4.w - (q2.x*xn0 + q2.w*xn1 + q3.z*xn2) - q4.x*xp1;
            float x2 = u2*q1.y;
            float x1 = (u1 - q1.x*x2)*q0.w;
            float x0 = (u0 - q0.y*x1 - q0.z*x2)*q0.x;
            ox[3*s] = x0; ox[3*s+1] = x1; ox[3*s+2] = x2;
            xp1 = xn1; xn0 = x0; xn1 = x1; xn2 = x2;
        }
    } else {
        float xn0=x20_, xn1=x21_, xn2=x22_, xp1=x11_;
        #pragma unroll
        for (int u = KH_-1; u >= 0; u--) {
            const float4* sp = sv4 + u*5;
            float4 q0 = sp[0], q1 = sp[1], q2 = sp[2], q3 = sp[3], q4 = sp[4];
            float u0 = q4.y - (q1.z*xn0 + q2.y*xn1 + q3.x*xn2);
            float u1 = q4.z - (q1.w*xn0 + q2.z*xn1 + q3.y*xn2) - q3.w*xp1;
            float u2 = q4.w - (q2.x*xn0 + q2.w*xn1 + q3.z*xn2) - q4.x*xp1;
            float x2 = u2*q1.y;
            float x1 = (u1 - q1.x*x2)*q0.w;
            float x0 = (u0 - q0.y*x1 - q0.z*x2)*q0.x;
            const int s = 29 - u;
            ox[3*s] = x0; ox[3*s+1] = x1; ox[3*s+2] = x2;
            xp1 = xn1; xn0 = x0; xn1 = x1; xn2 = x2;
        }
    }

    // ---- coalesced store-out ----
    __syncthreads();
    {
        const float4* s = (const float4*)s_co;
        float4* g = (float4*)(out + blk * 90);
        for (int k = tid; k < E_*90/4; k += TPB) g[k] = s[k];
    }
}

extern "C" void kernel_launch(void* const* d_in, const int* in_sizes, int n_in,
                              void* d_out, int out_size) {
    const float* coeffs = (const float*)d_in[0];
    const float* rhs    = (const float*)d_in[1];
    const float* iv_rhs = (const float*)d_in[2];
    const float* steps  = (const float*)d_in[3];
    float* out = (float*)d_out;

    dim3 block(TPB);
    dim3 grid(BS_ / E_);
    ode_babe_kernel<<<grid, block>>>(coeffs, rhs, iv_rhs, steps, out);
}

// round 7
// speedup vs baseline: 25.1733x; 1.0756x over previous
#include <cuda_runtime.h>

#define BS_  8192
#define NS_  30
#define KH_  14      // each side eliminates 14 blocks; interface blocks 14,15
#define E_   64      // elements per block
#define TPB  128     // threads 0-63: top halves, 64-127: bottom halves

// Generic streaming block elimination step (single code path, both directions).
#define ELIM_STEP(SVIDX) do {                                                    \
    float il00 = rsqrtf(D000);                                                   \
    float l10 = D010*il00, l20 = D020*il00;                                      \
    float il11 = rsqrtf(D011 - l10*l10);                                         \
    float l21 = (D021 - l20*l10)*il11;                                           \
    float il22 = rsqrtf(D022 - l20*l20 - l21*l21);                               \
    float w0,w1,w2;                                                              \
    w0 = A00*il00; w1 = (A01 - w0*l10)*il11; w2 = (A02 - w0*l20 - w1*l21)*il22;  \
    A00=w0; A01=w1; A02=w2;                                                      \
    w0 = A10*il00; w1 = (A11 - w0*l10)*il11; w2 = (A12 - w0*l20 - w1*l21)*il22;  \
    A10=w0; A11=w1; A12=w2;                                                      \
    w0 = A20*il00; w1 = (A21 - w0*l10)*il11; w2 = (A22 - w0*l20 - w1*l21)*il22;  \
    A20=w0; A21=w1; A22=w2;                                                      \
    m1 = m1*il11;                                                                \
    float m2 = -m1*l21*il22;                                                     \
    float y0 = r00*il00;                                                         \
    float y1 = (r01 - y0*l10)*il11;                                              \
    float y2 = (r02 - y0*l20 - y1*l21)*il22;                                     \
    r10 -= A00*y0 + A01*y1 + A02*y2;                                             \
    r11 -= A10*y0 + A11*y1 + A12*y2;                                             \
    r12 -= A20*y0 + A21*y1 + A22*y2;                                             \
    r21 -= m1*y1 + m2*y2;                                                        \
    D100 -= A00*A00 + A01*A01 + A02*A02;                                         \
    D110 -= A10*A00 + A11*A01 + A12*A02;                                         \
    D120 -= A20*A00 + A21*A01 + A22*A02;                                         \
    D111 -= A10*A10 + A11*A11 + A12*A12;                                         \
    D121 -= A20*A10 + A21*A11 + A22*A12;                                         \
    D122 -= A20*A20 + A21*A21 + A22*A22;                                         \
    B10 -= m1*A01 + m2*A02;                                                      \
    B11 -= m1*A11 + m2*A12;                                                      \
    B12 -= m1*A21 + m2*A22;                                                      \
    D211 -= m1*m1 + m2*m2;                                                       \
    float4* sp = sv4 + (SVIDX)*5;                                                \
    sp[0] = make_float4(il00, l10, l20, il11);                                   \
    sp[1] = make_float4(l21, il22, A00, A01);                                    \
    sp[2] = make_float4(A02, A10, A11, A12);                                     \
    sp[3] = make_float4(A20, A21, A22, m1);                                      \
    sp[4] = make_float4(m2, y0, y1, y2);                                         \
    D000=D100; D010=D110; D020=D120; D011=D111; D021=D121; D022=D122;            \
    D100=0; D110=0; D120=0; D111=D211; D121=0; D122=0; D211=0;                   \
    A00=0; A01=0; A02=0; A10=B10; A11=B11; A12=B12; A20=0; A21=0; A22=0;         \
    B10=0; B11=0; B12=0;                                                         \
    r00=r10; r01=r11; r02=r12;                                                   \
    r10=0; r11=r21; r12=0; r21=0;                                                \
} while(0)

__global__ __launch_bounds__(TPB)
void ode_babe_kernel(const float* __restrict__ coeffs,
                     const float* __restrict__ rhs,
                     const float* __restrict__ ivr,
                     const float* __restrict__ steps,
                     float* __restrict__ out)
{
    __shared__ float s_co[E_ * 90];   // coeffs in; reused for x out
    __shared__ float s_rr[E_ * 30];
    __shared__ float s_st[E_ * 29];
    __shared__ float s_iv[E_ * 4];
    __shared__ float s_ex[E_ * 2 * 16];   // interface exchange

    const int tid = threadIdx.x;
    const size_t blk = (size_t)blockIdx.x * E_;

    // ---- coalesced staging ----
    {
        const float4* g = (const float4*)(coeffs + blk * 90);
        float4* s = (float4*)s_co;
        for (int k = tid; k < E_*90/4; k += TPB) s[k] = g[k];
    }
    {
        const float4* g = (const float4*)(rhs + blk * 30);
        float4* s = (float4*)s_rr;
        for (int k = tid; k < E_*30/4; k += TPB) s[k] = g[k];
    }
    {
        const float4* g = (const float4*)(steps + blk * 29);
        float4* s = (float4*)s_st;
        for (int k = tid; k < E_*29/4; k += TPB) s[k] = g[k];
    }
    {
        const float4* g = (const float4*)(ivr + blk * 4);
        float4* s = (float4*)s_iv;
        for (int k = tid; k < E_*4/4; k += TPB) s[k] = g[k];
    }
    __syncthreads();

    const int  e   = tid & (E_ - 1);
    const bool top = tid < E_;

    const float* cc  = s_co + e * 90;
    const float* rrp = s_rr + e * 30;
    const float* stp = s_st + e * 29;

    // direction constants (uniform code path)
    const float sgn   = top ? 1.f : -1.f;
    const int   cbase = top ? 0 : 87;   // coeff float offset of step block
    const int   cstep = top ? 3 : -3;
    const int   rbase = top ? 0 : 29;
    const int   rstep = top ? 1 : -1;
    const int   hbase = top ? 0 : 28;
    const int   hstep = top ? 1 : -1;

    const float one_t = top ? 1.f : 0.f;
    const float iva0 = top ? s_iv[e*4+0] : 0.f;
    const float iva1 = top ? s_iv[e*4+1] : 0.f;
    const float iva2 = top ? s_iv[e*4+2] : 0.f;
    const float iva3 = top ? s_iv[e*4+3] : 0.f;

    float4 sv4[KH_ * 5];

    float D000=0,D010=0,D020=0,D011=0,D021=0,D022=0;
    float D100=0,D110=0,D120=0,D111=0,D121=0,D122=0;
    float D211=0;
    float A00=0,A01=0,A02=0,A10=0,A11=0,A12=0,A20=0,A21=0,A22=0;
    float B10=0,B11=0,B12=0;
    float r00=0,r01=0,r02=0, r10=0,r11=0,r12=0, r21=0;

    #pragma unroll
    for (int s = 0; s < KH_; s++) {
        const float* cb = cc + cbase + cstep*s;
        float c0=cb[0], c1=cb[1], c2=cb[2];
        float rv = rrp[rbase + rstep*s];

        D000 += c0*c0; D010 += c1*c0; D020 += c2*c0;
        D011 += c1*c1; D021 += c2*c1; D022 += c2*c2;
        r00 += c0*rv; r01 += c1*rv; r02 += c2*rv;
        if (s == 0) { D000 += one_t; D011 += one_t; r00 += iva0; r01 += iva1; }
        if (s == 1) { D000 += one_t; D011 += one_t; r00 += iva2; r01 += iva3; }

        float h = sgn * stp[hbase + hstep*s];
        float h2 = h*h, h3 = h2*h, h4 = h2*h2;
        D000 += 2.f;       D010 += h;          D020 += 0.5f*h2;
        D011 += 3.f*h2;    D021 += 1.5f*h3;    D022 += 1.25f*h4;
        A00  += -2.f;      A01  += -h;         A02  += -0.5f*h2;
        A10  += h;         A11  += -2.f*h2;    A12  += -h3;
        A20  += -0.5f*h2;  A21  += h3;
        D100 += 2.f;       D110 += -h;         D120 += 0.5f*h2;
        D111 += 3.f*h2;    D121 += -1.5f*h3;   D122 += 1.25f*h4;

        float cp = h + sgn * stp[hbase + hstep*(s+1)];
        D011 += 1.f;  A21 += cp;  float m1 = -1.f;
        D122 += cp*cp; B12 += -cp; D211 += 1.f;

        ELIM_STEP(s);
    }

    // ---- export window carries ----
    {
        float* ex = s_ex + (e*2 + (top ? 0 : 1)) * 16;
        ex[0]=D000; ex[1]=D010; ex[2]=D020; ex[3]=D011; ex[4]=D021; ex[5]=D022;
        ex[6]=D111;
        ex[7]=A10; ex[8]=A11; ex[9]=A12;
        ex[10]=r00; ex[11]=r01; ex[12]=r02;
        ex[13]=r11;
    }
    __syncthreads();

    // ---- interface: 6x6 SPD solve for x_14, x_15 (computed by both threads) ----
    float x10_, x11_, x12_, x20_, x21_, x22_;
    {
        const float* te = s_ex + (e*2 + 0) * 16;
        const float* be = s_ex + (e*2 + 1) * 16;
        float h = stp[KH_];
        float h2 = h*h, h3 = h2*h, h4 = h2*h2;
        float cK0=cc[3*KH_], cK1=cc[3*KH_+1], cK2=cc[3*KH_+2];
        float cL0=cc[3*KH_+3], cL1=cc[3*KH_+4], cL2=cc[3*KH_+5];
        float rvK = rrp[KH_], rvL = rrp[KH_+1];

        float d00 = te[0] + cK0*cK0 + 2.f;
        float d10 = te[1] + cK1*cK0 + h;
        float d20 = te[2] + cK2*cK0 + 0.5f*h2;
        float d11 = te[3] + cK1*cK1 + 3.f*h2 + be[6];
        float d21 = te[4] + cK2*cK1 + 1.5f*h3;
        float d22 = te[5] + cK2*cK2 + 1.25f*h4;
        float e00 = be[0] + cL0*cL0 + 2.f;
        float e10 = be[1] + cL1*cL0 - h;
        float e20 = be[2] + cL2*cL0 + 0.5f*h2;
        float e11 = be[3] + cL1*cL1 + 3.f*h2 + te[6];
        float e21 = be[4] + cL2*cL1 - 1.5f*h3;
        float e22 = be[5] + cL2*cL2 + 1.25f*h4;
        float a00 = -2.f;
        float a01 = -h        + be[7];
        float a02 = -0.5f*h2;
        float a10 =  h        + te[7];
        float a11 = -2.f*h2   + te[8] + be[8];
        float a12 = -h3       + te[9];
        float a20 = -0.5f*h2;
        float a21 =  h3       + be[9];
        float a22 = 0.f;
        float rk0 = te[10] + cK0*rvK;
        float rk1 = te[11] + cK1*rvK + be[13];
        float rk2 = te[12] + cK2*rvK;
        float rl0 = be[10] + cL0*rvL;
        float rl1 = be[11] + cL1*rvL + te[13];
        float rl2 = be[12] + cL2*rvL;

        float il00 = rsqrtf(d00);
        float l10 = d10*il00, l20 = d20*il00;
        float il11 = rsqrtf(d11 - l10*l10);
        float l21 = (d21 - l20*l10)*il11;
        float il22 = rsqrtf(d22 - l20*l20 - l21*l21);
        float w00 = a00*il00, w01 = (a01 - w00*l10)*il11, w02 = (a02 - w00*l20 - w01*l21)*il22;
        float w10 = a10*il00, w11 = (a11 - w10*l10)*il11, w12 = (a12 - w10*l20 - w11*l21)*il22;
        float w20 = a20*il00, w21 = (a21 - w20*l10)*il11, w22 = (a22 - w20*l20 - w21*l21)*il22;
        float s00 = e00 - (w00*w00 + w01*w01 + w02*w02);
        float s10 = e10 - (w10*w00 + w11*w01 + w12*w02);
        float s20 = e20 - (w20*w00 + w21*w01 + w22*w02);
        float s11 = e11 - (w10*w10 + w11*w11 + w12*w12);
        float s21 = e21 - (w20*w10 + w21*w11 + w22*w12);
        float s22 = e22 - (w20*w20 + w21*w21 + w22*w22);
        float jl00 = rsqrtf(s00);
        float k10 = s10*jl00, k20 = s20*jl00;
        float jl11 = rsqrtf(s11 - k10*k10);
        float k21 = (s21 - k20*k10)*jl11;
        float jl22 = rsqrtf(s22 - k20*k20 - k21*k21);
        float y10 = rk0*il00;
        float y11 = (rk1 - y10*l10)*il11;
        float y12 = (rk2 - y10*l20 - y11*l21)*il22;
        float t0 = rl0 - (w00*y10 + w01*y11 + w02*y12);
        float t1 = rl1 - (w10*y10 + w11*y11 + w12*y12);
        float t2 = rl2 - (w20*y10 + w21*y11 + w22*y12);
        float y20 = t0*jl00;
        float y21 = (t1 - y20*k10)*jl11;
        float y22 = (t2 - y20*k20 - y21*k21)*jl22;
        x22_ = y22*jl22;
        x21_ = (y21 - k21*x22_)*jl11;
        x20_ = (y20 - k10*x21_ - k20*x22_)*jl00;
        float z0 = y10 - (w00*x20_ + w10*x21_ + w20*x22_);
        float z1 = y11 - (w01*x20_ + w11*x21_ + w21*x22_);
        float z2 = y12 - (w02*x20_ + w12*x21_ + w22*x22_);
        x12_ = z2*il22;
        x11_ = (z1 - l21*x12_)*il11;
        x10_ = (z0 - l10*x11_ - l20*x12_)*il00;
    }

    // ---- back substitution (uniform code path) ----
    float* ox = s_co + e * 90;   // coeffs consumed; reuse as output staging
    if (top) {
        ox[3*KH_+0]=x10_; ox[3*KH_+1]=x11_; ox[3*KH_+2]=x12_;
        ox[3*KH_+3]=x20_; ox[3*KH_+4]=x21_; ox[3*KH_+5]=x22_;
    }
    float xn0 = top ? x10_ : x20_;
    float xn1 = top ? x11_ : x21_;
    float xn2 = top ? x12_ : x22_;
    float xp1 = top ? x21_ : x11_;
    const int obase = top ? 0 : 87;
    const int ostep = top ? 3 : -3;

    #pragma unroll
    for (int k = KH_-1; k >= 0; k--) {
        const float4* sp = sv4 + k*5;
        float4 q0 = sp[0], q1 = sp[1], q2 = sp[2], q3 = sp[3], q4 = sp[4];
        float u0 = q4.y - (q1.z*xn0 + q2.y*xn1 + q3.x*xn2);
        float u1 = q4.z - (q1.w*xn0 + q2.z*xn1 + q3.y*xn2) - q3.w*xp1;
        float u2 = q4.w - (q2.x*xn0 + q2.w*xn1 + q3.z*xn2) - q4.x*xp1;
        float x2 = u2*q1.y;
        float x1 = (u1 - q1.x*x2)*q0.w;
        float x0 = (u0 - q0.y*x1 - q0.z*x2)*q0.x;
        float* op = ox + obase + ostep*k;
        op[0] = x0; op[1] = x1; op[2] = x2;
        xp1 = xn1; xn0 = x0; xn1 = x1; xn2 = x2;
    }

    // ---- coalesced store-out ----
    __syncthreads();
    {
        const float4* s = (const float4*)s_co;
        float4* g = (float4*)(out + blk * 90);
        for (int k = tid; k < E_*90/4; k += TPB) g[k] = s[k];
    }
}

extern "C" void kernel_launch(void* const* d_in, const int* in_sizes, int n_in,
                              void* d_out, int out_size) {
    const float* coeffs = (const float*)d_in[0];
    const float* rhs    = (const float*)d_in[1];
    const float* iv_rhs = (const float*)d_in[2];
    const float* steps  = (const float*)d_in[3];
    float* out = (float*)d_out;

    dim3 block(TPB);
    dim3 grid(BS_ / E_);
    ode_babe_kernel<<<grid, block>>>(coeffs, rhs, iv_rhs, steps, out);
}